// round 15
// baseline (speedup 1.0000x reference)
#include <cuda_runtime.h>
#include <cuda_bf16.h>
#include <cstdint>

// ============================================================================
// CrossDepthAttention, mma.sync tensor cores (base-target legal).
//   P0: cur -> bf16; {Wq,Wv,Wo} -> bf16 (one launch); Wk -> transpose+bf16
//   K1: q    = cur @ Wq^T            bf16 BN=64 (3 CTAs/SM)
//   K2: qk_h = q_h @ Wk_h            bf16 persistent j-loop (dedicated stage)
//   K3: fused attention (2 barriers, multi-value butterfly) -> hbar bf16
//   K4: out_h = hbar_h @ Wv_h^T      bf16 BN=64 -> out bf16
//   K5: final = cur + out @ Wo^T     bf16 BN=64 + fp32 residual
// ============================================================================

#define D_DIM   1024
#define H_HEADS 16
#define HD      64
#define NPREV   8
#define M_MAX   8192

__device__ __nv_bfloat16 g_cb[M_MAX * D_DIM];                      // cur (bf16)
__device__ __nv_bfloat16 g_qb[M_MAX * D_DIM];                      // q (bf16)
__device__ __nv_bfloat16 g_qk[(size_t)M_MAX * H_HEADS * D_DIM];    // qk (bf16)
__device__ __nv_bfloat16 g_hb[(size_t)M_MAX * H_HEADS * D_DIM];    // hbar (bf16)
__device__ __nv_bfloat16 g_ob[M_MAX * D_DIM];                      // out (bf16)
__device__ __nv_bfloat16 g_wq[D_DIM * D_DIM];                      // Wq (bf16)
__device__ __nv_bfloat16 g_wkt[D_DIM * D_DIM];                     // Wk^T (bf16)
__device__ __nv_bfloat16 g_wv[D_DIM * D_DIM];                      // Wv (bf16)
__device__ __nv_bfloat16 g_wo[D_DIM * D_DIM];                      // Wo (bf16)

// ---------------------------------------------------------------------------
__device__ __forceinline__ uint32_t smem_u32(const void* p) {
    uint32_t a;
    asm("{ .reg .u64 t; cvta.to.shared.u64 t, %1; cvt.u32.u64 %0, t; }"
        : "=r"(a) : "l"(p));
    return a;
}
__device__ __forceinline__ void cp16(uint32_t s, const void* g) {
    asm volatile("cp.async.cg.shared.global [%0], [%1], 16;\n" :: "r"(s), "l"(g));
}
__device__ __forceinline__ void cp_commit() {
    asm volatile("cp.async.commit_group;\n" ::: "memory");
}
template <int N> __device__ __forceinline__ void cp_wait() {
    asm volatile("cp.async.wait_group %0;\n" :: "n"(N) : "memory");
}
__device__ __forceinline__ void mma_bf16(float* c, const uint32_t* a,
                                         const uint32_t* b) {
    asm volatile(
        "mma.sync.aligned.m16n8k16.row.col.f32.bf16.bf16.f32 "
        "{%0,%1,%2,%3}, {%4,%5,%6,%7}, {%8,%9}, {%0,%1,%2,%3};\n"
        : "+f"(c[0]), "+f"(c[1]), "+f"(c[2]), "+f"(c[3])
        : "r"(a[0]), "r"(a[1]), "r"(a[2]), "r"(a[3]), "r"(b[0]), "r"(b[1]));
}
__device__ __forceinline__ void ldsm_x4(uint32_t& r0, uint32_t& r1,
                                        uint32_t& r2, uint32_t& r3,
                                        uint32_t addr) {
    asm volatile("ldmatrix.sync.aligned.m8n8.x4.shared.b16 {%0,%1,%2,%3}, [%4];"
                 : "=r"(r0), "=r"(r1), "=r"(r2), "=r"(r3) : "r"(addr));
}
__device__ __forceinline__ uint32_t pack_bf162(float lo, float hi) {
    __nv_bfloat162 p = __float22bfloat162_rn(make_float2(lo, hi));
    return *reinterpret_cast<uint32_t*>(&p);
}

// ---------------------------------------------------------------------------
// P0a: Wk transpose + bf16 convert, tiled 32x32.
// ---------------------------------------------------------------------------
__global__ void __launch_bounds__(256) transpose_wk_bf16(
    const float* __restrict__ in, __nv_bfloat16* __restrict__ outp)
{
    __shared__ float t[32][33];
    const int bx = blockIdx.x * 32, by = blockIdx.y * 32;
    int x = bx + threadIdx.x;
#pragma unroll
    for (int i = 0; i < 32; i += 8)
        t[threadIdx.y + i][threadIdx.x] = in[(size_t)(by + threadIdx.y + i) * D_DIM + x];
    __syncthreads();
    x = by + threadIdx.x;
#pragma unroll
    for (int i = 0; i < 32; i += 8)
        outp[(size_t)(bx + threadIdx.y + i) * D_DIM + x] =
            __float2bfloat16(t[threadIdx.x][threadIdx.y + i]);
}

// P0b: fp32 -> bf16, single tensor (cur)
__global__ void __launch_bounds__(256) convert_f2b(
    const float* __restrict__ in, __nv_bfloat16* __restrict__ outp)
{
    int i = (blockIdx.x * 256 + threadIdx.x) * 4;
    float4 a = *(const float4*)(in + i);
    *(__nv_bfloat162*)(outp + i)     = __float22bfloat162_rn(make_float2(a.x, a.y));
    *(__nv_bfloat162*)(outp + i + 2) = __float22bfloat162_rn(make_float2(a.z, a.w));
}

// P0c: fp32 -> bf16 for three weight matrices in one launch
__global__ void __launch_bounds__(256) convert_w3(
    const float* __restrict__ w0, __nv_bfloat16* __restrict__ o0,
    const float* __restrict__ w1, __nv_bfloat16* __restrict__ o1,
    const float* __restrict__ w2, __nv_bfloat16* __restrict__ o2)
{
    const float* in;
    __nv_bfloat16* outp;
    if (blockIdx.y == 0)      { in = w0; outp = o0; }
    else if (blockIdx.y == 1) { in = w1; outp = o1; }
    else                      { in = w2; outp = o2; }
    int i = (blockIdx.x * 256 + threadIdx.x) * 4;
    float4 a = *(const float4*)(in + i);
    *(__nv_bfloat162*)(outp + i)     = __float22bfloat162_rn(make_float2(a.x, a.y));
    *(__nv_bfloat162*)(outp + i + 2) = __float22bfloat162_rn(make_float2(a.z, a.w));
}

// ---------------------------------------------------------------------------
// bf16 m16n8k16 GEMM (NT), ldmatrix loads.
//   OUT_BF16 epilogue: staged through SMEM aliased onto the (dead) mainloop
//   buffers. CTA tile 128 x BN, BK=64 halves, 256 threads, stride 72 halves.
// ---------------------------------------------------------------------------
template <int BN, bool OUT_BF16, bool RESID>
__global__ void __launch_bounds__(256)
gemm_bf16(const __nv_bfloat16* __restrict__ A, int lda, long long sA,
          const __nv_bfloat16* __restrict__ B, int ldb, long long sB,
          const float* __restrict__ R,
          void* __restrict__ C, int ldc, long long sC, int K)
{
    constexpr int WM = (BN == 128) ? 2 : 4;
    constexpr int MT = 8 / WM;
    constexpr int A_HALVES = 128 * 72;
    constexpr int B_HALVES = BN * 72;
    constexpr int STW = BN + 8;                    // stage stride (halves)

    extern __shared__ __align__(16) __nv_bfloat16 sm_h[];
    const uint32_t sbase = smem_u32(sm_h);

    const int tid = threadIdx.x;
    const int wid = tid >> 5, lane = tid & 31;
    const int wm = wid % WM, wn = wid / WM;
    const int bx = blockIdx.x, by = blockIdx.y, bz = blockIdx.z;

    const __nv_bfloat16* Ah = A + (long long)bz * sA + (size_t)(by * 128) * lda;
    const __nv_bfloat16* Bh = B + (long long)bz * sB + (size_t)(bx * BN) * ldb;

    auto fill = [&](int buf, int k0) {
        const uint32_t Ab = sbase + (uint32_t)(buf * A_HALVES) * 2u;
        const uint32_t Bb = sbase + (uint32_t)(2 * A_HALVES + buf * B_HALVES) * 2u;
#pragma unroll
        for (int p = 0; p < 4; ++p) {
            int ch = tid + p * 256;
            int row = ch >> 3, c8 = ch & 7;
            cp16(Ab + (uint32_t)(row * 72 + c8 * 8) * 2u,
                 Ah + (size_t)row * lda + k0 + c8 * 8);
        }
#pragma unroll
        for (int p = 0; p < BN * 8 / 256; ++p) {
            int ch = tid + p * 256;
            int row = ch >> 3, c8 = ch & 7;
            cp16(Bb + (uint32_t)(row * 72 + c8 * 8) * 2u,
                 Bh + (size_t)row * ldb + k0 + c8 * 8);
        }
    };

    float acc[MT][4][4];
#pragma unroll
    for (int mt = 0; mt < MT; ++mt)
#pragma unroll
        for (int nt = 0; nt < 4; ++nt)
#pragma unroll
            for (int j = 0; j < 4; ++j) acc[mt][nt][j] = 0.0f;

    // ldmatrix lane address bases (in halves)
    const int r8 = lane & 7;
    const int a_base_h = (wm * (128 / WM) + ((lane >> 3) & 1) * 8 + r8) * 72
                       + ((lane >> 4) & 1) * 8;
    const int b_sel = (lane >> 3) & 3;
    const int b_base_h = (wn * 32 + (b_sel >> 1) * 8 + r8) * 72 + (b_sel & 1) * 8;

    const int NC = K / 64;
    fill(0, 0);
    cp_commit();

    for (int c = 0; c < NC; ++c) {
        if (c + 1 < NC) { fill((c + 1) & 1, (c + 1) * 64); cp_commit(); cp_wait<1>(); }
        else            { cp_wait<0>(); }
        __syncthreads();

        const int buf = c & 1;
        const uint32_t Ab = sbase + (uint32_t)(buf * A_HALVES) * 2u;
        const uint32_t Bb = sbase + (uint32_t)(2 * A_HALVES + buf * B_HALVES) * 2u;

#pragma unroll
        for (int s = 0; s < 4; ++s) {
            uint32_t af[MT][4];
#pragma unroll
            for (int mt = 0; mt < MT; ++mt)
                ldsm_x4(af[mt][0], af[mt][1], af[mt][2], af[mt][3],
                        Ab + (uint32_t)(a_base_h + mt * 16 * 72 + s * 16) * 2u);
            uint32_t bfr[4][2];
#pragma unroll
            for (int ntp = 0; ntp < 2; ++ntp)
                ldsm_x4(bfr[2 * ntp][0], bfr[2 * ntp][1],
                        bfr[2 * ntp + 1][0], bfr[2 * ntp + 1][1],
                        Bb + (uint32_t)(b_base_h + ntp * 16 * 72 + s * 16) * 2u);
#pragma unroll
            for (int mt = 0; mt < MT; ++mt)
#pragma unroll
                for (int nt = 0; nt < 4; ++nt)
                    mma_bf16(acc[mt][nt], af[mt], bfr[nt]);
        }
        __syncthreads();
    }

    const int g = lane >> 2, tg = lane & 3;
    if (!OUT_BF16) {
        const int row0 = by * 128 + wm * (128 / WM) + g;
        const int coll = wn * 32 + tg * 2;
#pragma unroll
        for (int mt = 0; mt < MT; ++mt) {
            const int m = row0 + mt * 16;
#pragma unroll
            for (int nt = 0; nt < 4; ++nt) {
                const int n = bx * BN + coll + nt * 8;
                float* Cg = (float*)C + (long long)bz * sC;
                float2 v0 = make_float2(acc[mt][nt][0], acc[mt][nt][1]);
                float2 v1 = make_float2(acc[mt][nt][2], acc[mt][nt][3]);
                if (RESID) {
                    float2 r0 = *(const float2*)(R + (size_t)m * ldc + n);
                    float2 r1 = *(const float2*)(R + (size_t)(m + 8) * ldc + n);
                    v0.x += r0.x; v0.y += r0.y;
                    v1.x += r1.x; v1.y += r1.y;
                }
                *(float2*)(Cg + (size_t)m * ldc + n)       = v0;
                *(float2*)(Cg + (size_t)(m + 8) * ldc + n) = v1;
            }
        }
    } else {
        // staged epilogue ALIASED onto mainloop buffers (dead after last sync)
        __nv_bfloat16* stg = sm_h;
        const int ml0 = wm * (128 / WM) + g;
        const int nl0 = wn * 32 + tg * 2;
#pragma unroll
        for (int mt = 0; mt < MT; ++mt) {
            const int ml = ml0 + mt * 16;
#pragma unroll
            for (int nt = 0; nt < 4; ++nt) {
                const int nl = nl0 + nt * 8;
                *(uint32_t*)&stg[ml * STW + nl] =
                    pack_bf162(acc[mt][nt][0], acc[mt][nt][1]);
                *(uint32_t*)&stg[(ml + 8) * STW + nl] =
                    pack_bf162(acc[mt][nt][2], acc[mt][nt][3]);
            }
        }
        __syncthreads();
        __nv_bfloat16* Cg = (__nv_bfloat16*)C + (long long)bz * sC;
#pragma unroll
        for (int p = 0; p < 128 * BN / 8 / 256; ++p) {
            int ch = tid + p * 256;
            int row = ch / (BN / 8), c8 = ch % (BN / 8);
            uint4 v = *(uint4*)&stg[row * STW + c8 * 8];
            *(uint4*)(Cg + (size_t)(by * 128 + row) * ldc + bx * BN + c8 * 8) = v;
        }
    }
}

// ---------------------------------------------------------------------------
// K2: persistent j-loop bf16 GEMM, ldmatrix, dedicated SMEM stage.
//   qk[m, h*1024 + j] = sum_d q[m, h*64+d] * wkt[j, h*64+d]
// ---------------------------------------------------------------------------
__global__ void __launch_bounds__(256)
gemm_k2(const __nv_bfloat16* __restrict__ Q,
        const __nv_bfloat16* __restrict__ WKT,
        __nv_bfloat16* __restrict__ QK)
{
    constexpr int A_HALVES = 128 * 72;
    constexpr int B_HALVES = 128 * 72;
    constexpr int STW = 136;                       // stage stride (halves)

    extern __shared__ __align__(16) __nv_bfloat16 sm_h[];
    const uint32_t sbase = smem_u32(sm_h);

    const int tid = threadIdx.x;
    const int wid = tid >> 5, lane = tid & 31;
    const int wm = wid & 1, wn = wid >> 1;
    const int by = blockIdx.x;           // m-tile
    const int h  = blockIdx.y;           // head

    const __nv_bfloat16* Ah = Q + (size_t)(by * 128) * D_DIM + h * HD;
    const __nv_bfloat16* Bh = WKT + h * HD;

    // A: 128 rows x 64 halves = 1024 chunks of 16B (4 per thread)
#pragma unroll
    for (int p = 0; p < 4; ++p) {
        int ch = tid + p * 256;
        int row = ch >> 3, c8 = ch & 7;
        cp16(sbase + (uint32_t)(row * 72 + c8 * 8) * 2u,
             Ah + (size_t)row * D_DIM + c8 * 8);
    }
    auto fillB = [&](int buf, int j0) {
        const uint32_t Bb = sbase + (uint32_t)(A_HALVES + buf * B_HALVES) * 2u;
#pragma unroll
        for (int p = 0; p < 4; ++p) {
            int ch = tid + p * 256;
            int row = ch >> 3, c8 = ch & 7;
            cp16(Bb + (uint32_t)(row * 72 + c8 * 8) * 2u,
                 Bh + (size_t)(j0 + row) * D_DIM + c8 * 8);
        }
    };
    fillB(0, 0);
    cp_commit();        // group 0: A + B0

    // ldmatrix bases
    const int r8 = lane & 7;
    const int a_base_h = (wm * 64 + ((lane >> 3) & 1) * 8 + r8) * 72
                       + ((lane >> 4) & 1) * 8;
    const int b_sel = (lane >> 3) & 3;
    const int b_base_h = (wn * 32 + (b_sel >> 1) * 8 + r8) * 72 + (b_sel & 1) * 8;

    const int g = lane >> 2, tg = lane & 3;
    __nv_bfloat16* stg = sm_h + A_HALVES + 2 * B_HALVES;

    for (int jt = 0; jt < 8; ++jt) {
        if (jt + 1 < 8) { fillB((jt + 1) & 1, (jt + 1) * 128); cp_commit(); cp_wait<1>(); }
        else            { cp_wait<0>(); }
        __syncthreads();

        const uint32_t Bb = sbase + (uint32_t)(A_HALVES + (jt & 1) * B_HALVES) * 2u;

        float acc[4][4][4];
#pragma unroll
        for (int mt = 0; mt < 4; ++mt)
#pragma unroll
            for (int nt = 0; nt < 4; ++nt)
#pragma unroll
                for (int j = 0; j < 4; ++j) acc[mt][nt][j] = 0.0f;

#pragma unroll
        for (int s = 0; s < 4; ++s) {              // 4 x k16 over K=64
            uint32_t af[4][4];
#pragma unroll
            for (int mt = 0; mt < 4; ++mt)
                ldsm_x4(af[mt][0], af[mt][1], af[mt][2], af[mt][3],
                        sbase + (uint32_t)(a_base_h + mt * 16 * 72 + s * 16) * 2u);
            uint32_t bfr[4][2];
#pragma unroll
            for (int ntp = 0; ntp < 2; ++ntp)
                ldsm_x4(bfr[2 * ntp][0], bfr[2 * ntp][1],
                        bfr[2 * ntp + 1][0], bfr[2 * ntp + 1][1],
                        Bb + (uint32_t)(b_base_h + ntp * 16 * 72 + s * 16) * 2u);
#pragma unroll
            for (int mt = 0; mt < 4; ++mt)
#pragma unroll
                for (int nt = 0; nt < 4; ++nt)
                    mma_bf16(acc[mt][nt], af[mt], bfr[nt]);
        }

        // staged epilogue for this j-tile
        const int ml0 = wm * 64 + g;
        const int nl0 = wn * 32 + tg * 2;
#pragma unroll
        for (int mt = 0; mt < 4; ++mt) {
            const int ml = ml0 + mt * 16;
#pragma unroll
            for (int nt = 0; nt < 4; ++nt) {
                const int nl = nl0 + nt * 8;
                *(uint32_t*)&stg[ml * STW + nl] =
                    pack_bf162(acc[mt][nt][0], acc[mt][nt][1]);
                *(uint32_t*)&stg[(ml + 8) * STW + nl] =
                    pack_bf162(acc[mt][nt][2], acc[mt][nt][3]);
            }
        }
        __syncthreads();
        __nv_bfloat16* Cg = QK + (size_t)h * D_DIM + (size_t)jt * 128;
#pragma unroll
        for (int p = 0; p < 8; ++p) {
            int ch = tid + p * 256;
            int row = ch >> 4, c8 = ch & 15;
            uint4 v = *(uint4*)&stg[row * STW + c8 * 8];
            *(uint4*)(Cg + (size_t)(by * 128 + row) * (H_HEADS * D_DIM) + c8 * 8) = v;
        }
    }
}

// ---------------------------------------------------------------------------
// K3: fused attention — 2 barriers + multi-value butterfly. hbar -> bf16.
// ---------------------------------------------------------------------------
__global__ void __launch_bounds__(256) attn_kernel(
    const float* __restrict__ hist, const __nv_bfloat16* __restrict__ qk,
    __nv_bfloat16* __restrict__ hbar)
{
    __shared__ float red[H_HEADS][NPREV][8];
    __shared__ __align__(16) float attn_s[H_HEADS][NPREV];

    const int m    = blockIdx.x;
    const int tid  = threadIdx.x;
    const int lane = tid & 31;
    const int warp = tid >> 5;

    const __nv_bfloat16* qrow = qk + (size_t)m * (H_HEADS * D_DIM) + tid * 4;
    uint2 q2[H_HEADS];
#pragma unroll
    for (int h = 0; h < H_HEADS; h++)
        q2[h] = *(const uint2*)(qrow + h * D_DIM);

    float4 hv[NPREV];
    const float* hg = hist + (size_t)m * NPREV * D_DIM + tid * 4;
#pragma unroll
    for (int n = 0; n < NPREV; n++)
        hv[n] = *(const float4*)(hg + n * D_DIM);

    // ---- Phase A: dots + multi-value butterfly reduction ----
#pragma unroll
    for (int h = 0; h < H_HEADS; h++) {
        float2 qa = __bfloat1622float2(*reinterpret_cast<__nv_bfloat162*>(&q2[h].x));
        float2 qb = __bfloat1622float2(*reinterpret_cast<__nv_bfloat162*>(&q2[h].y));
        float p[NPREV];
#pragma unroll
        for (int n = 0; n < NPREV; n++)
            p[n] = qa.x * hv[n].x + qa.y * hv[n].y
                 + qb.x * hv[n].z + qb.y * hv[n].w;

#pragma unroll
        for (int i = 0; i < 4; i++) {
            float send = (lane & 16) ? p[i] : p[i + 4];
            float recv = __shfl_xor_sync(0xffffffffu, send, 16);
            p[i] = ((lane & 16) ? p[i + 4] : p[i]) + recv;
        }
#pragma unroll
        for (int i = 0; i < 2; i++) {
            float send = (lane & 8) ? p[i] : p[i + 2];
            float recv = __shfl_xor_sync(0xffffffffu, send, 8);
            p[i] = ((lane & 8) ? p[i + 2] : p[i]) + recv;
        }
        {
            float send = (lane & 4) ? p[0] : p[1];
            float recv = __shfl_xor_sync(0xffffffffu, send, 4);
            p[0] = ((lane & 4) ? p[1] : p[0]) + recv;
        }
        p[0] += __shfl_xor_sync(0xffffffffu, p[0], 2);
        p[0] += __shfl_xor_sync(0xffffffffu, p[0], 1);
        if ((lane & 3) == 0) red[h][lane >> 2][warp] = p[0];
    }
    __syncthreads();

    // ---- Phase B: 16 parallel softmaxes ----
    if (tid < H_HEADS) {
        const int h = tid;
        float lg[NPREV];
        float mx = -1e30f;
#pragma unroll
        for (int n = 0; n < NPREV; n++) {
            float4 s0 = *(const float4*)&red[h][n][0];
            float4 s1 = *(const float4*)&red[h][n][4];
            float s = (s0.x + s0.y) + (s0.z + s0.w)
                    + (s1.x + s1.y) + (s1.z + s1.w);
            lg[n] = s * 0.125f;
            mx = fmaxf(mx, lg[n]);
        }
        float den = 0.0f;
#pragma unroll
        for (int n = 0; n < NPREV; n++) { lg[n] = expf(lg[n] - mx); den += lg[n]; }
        float inv = 1.0f / den;
#pragma unroll
        for (int n = 0; n < NPREV; n++) attn_s[h][n] = lg[n] * inv;
    }
    __syncthreads();

    // ---- Phase C: weighted sums + bf16 stores ----
    __nv_bfloat16* orow = hbar + (size_t)m * (H_HEADS * D_DIM) + tid * 4;
#pragma unroll
    for (int h = 0; h < H_HEADS; h++) {
        float4 w0 = *(const float4*)&attn_s[h][0];
        float4 w1 = *(const float4*)&attn_s[h][4];
        float4 a4;
        a4.x = w0.x * hv[0].x; a4.y = w0.x * hv[0].y;
        a4.z = w0.x * hv[0].z; a4.w = w0.x * hv[0].w;
        a4.x = fmaf(w0.y, hv[1].x, a4.x); a4.y = fmaf(w0.y, hv[1].y, a4.y);
        a4.z = fmaf(w0.y, hv[1].z, a4.z); a4.w = fmaf(w0.y, hv[1].w, a4.w);
        a4.x = fmaf(w0.z, hv[2].x, a4.x); a4.y = fmaf(w0.z, hv[2].y, a4.y);
        a4.z = fmaf(w0.z, hv[2].z, a4.z); a4.w = fmaf(w0.z, hv[2].w, a4.w);
        a4.x = fmaf(w0.w, hv[3].x, a4.x); a4.y = fmaf(w0.w, hv[3].y, a4.y);
        a4.z = fmaf(w0.w, hv[3].z, a4.z); a4.w = fmaf(w0.w, hv[3].w, a4.w);
        a4.x = fmaf(w1.x, hv[4].x, a4.x); a4.y = fmaf(w1.x, hv[4].y, a4.y);
        a4.z = fmaf(w1.x, hv[4].z, a4.z); a4.w = fmaf(w1.x, hv[4].w, a4.w);
        a4.x = fmaf(w1.y, hv[5].x, a4.x); a4.y = fmaf(w1.y, hv[5].y, a4.y);
        a4.z = fmaf(w1.y, hv[5].z, a4.z); a4.w = fmaf(w1.y, hv[5].w, a4.w);
        a4.x = fmaf(w1.z, hv[6].x, a4.x); a4.y = fmaf(w1.z, hv[6].y, a4.y);
        a4.z = fmaf(w1.z, hv[6].z, a4.z); a4.w = fmaf(w1.z, hv[6].w, a4.w);
        a4.x = fmaf(w1.w, hv[7].x, a4.x); a4.y = fmaf(w1.w, hv[7].y, a4.y);
        a4.z = fmaf(w1.w, hv[7].z, a4.z); a4.w = fmaf(w1.w, hv[7].w, a4.w);
        uint2 ov;
        ov.x = pack_bf162(a4.x, a4.y);
        ov.y = pack_bf162(a4.z, a4.w);
        *(uint2*)(orow + h * D_DIM) = ov;
    }
}

// ---------------------------------------------------------------------------
extern "C" void kernel_launch(void* const* d_in, const int* in_sizes, int n_in,
                              void* d_out, int out_size)
{
    const float* cur  = (const float*)d_in[0];
    const float* hist = (const float*)d_in[1];
    const float* Wq   = (const float*)d_in[2];
    const float* Wk   = (const float*)d_in[3];
    const float* Wv   = (const float*)d_in[4];
    const float* Wo   = (const float*)d_in[5];
    float* out = (float*)d_out;

    const int D = D_DIM;
    const int M = in_sizes[0] / D;   // 8192

    __nv_bfloat16 *cb = nullptr, *qb = nullptr, *qk = nullptr, *hb = nullptr;
    __nv_bfloat16 *ob = nullptr, *wq = nullptr, *wkt = nullptr, *wv = nullptr, *wo = nullptr;
    cudaGetSymbolAddress((void**)&cb,  g_cb);
    cudaGetSymbolAddress((void**)&qb,  g_qb);
    cudaGetSymbolAddress((void**)&qk,  g_qk);
    cudaGetSymbolAddress((void**)&hb,  g_hb);
    cudaGetSymbolAddress((void**)&ob,  g_ob);
    cudaGetSymbolAddress((void**)&wq,  g_wq);
    cudaGetSymbolAddress((void**)&wkt, g_wkt);
    cudaGetSymbolAddress((void**)&wv,  g_wv);
    cudaGetSymbolAddress((void**)&wo,  g_wo);

    // SMEM budgets (bytes)
    constexpr int SM_K2  = (128 * 72 + 2 * (128 * 72) + 128 * 136) * 2;  // 90112
    constexpr int SM_B64 = (2 * (128 * 72) + 2 * (64 * 72)) * 2;         // 55296

    cudaFuncSetAttribute(gemm_k2,
                         cudaFuncAttributeMaxDynamicSharedMemorySize, SM_K2);
    cudaFuncSetAttribute(gemm_bf16<64, true,  false>,
                         cudaFuncAttributeMaxDynamicSharedMemorySize, SM_B64);
    cudaFuncSetAttribute(gemm_bf16<64, false, true>,
                         cudaFuncAttributeMaxDynamicSharedMemorySize, SM_B64);

    // P0: conversions
    convert_f2b<<<M * D / 4 / 256, 256>>>(cur, cb);
    convert_w3<<<dim3(D * D / 4 / 256, 3), 256>>>(Wq, wq, Wv, wv, Wo, wo);
    transpose_wk_bf16<<<dim3(32, 32), dim3(32, 8)>>>(Wk, wkt);

    // K1: q = cur @ Wq^T  (bf16, BN=64, 3 CTAs/SM) -> bf16
    gemm_bf16<64, true, false>
        <<<dim3(D / 64, M / 128, 1), 256, SM_B64>>>(
            cb, D, 0, wq, D, 0, nullptr, qb, D, 0, D);

    // K2: qk_h = q_h @ Wk_h  (bf16, persistent j-loop, staged) -> bf16
    gemm_k2<<<dim3(M / 128, H_HEADS), 256, SM_K2>>>(qb, wkt, qk);

    // K3: attention -> hbar (bf16)
    attn_kernel<<<M, 256>>>(hist, qk, hb);

    // K4: out_h = hbar_h @ Wv_h^T (bf16, BN=64) -> out bf16
    gemm_bf16<64, true, false>
        <<<dim3(1, M / 128, H_HEADS), 256, SM_B64>>>(
            hb, H_HEADS * D, D,
            wv, D, (long long)HD * D,
            nullptr,
            ob, D, HD,
            D);

    // K5: final = cur + out @ Wo^T  (bf16, BN=64 + fp32 residual)
    gemm_bf16<64, false, true>
        <<<dim3(D / 64, M / 128, 1), 256, SM_B64>>>(
            ob, D, 0, wo, D, 0, cur, out, D, 0, D);
}

// round 16
// speedup vs baseline: 1.4417x; 1.4417x over previous
#include <cuda_runtime.h>
#include <cuda_bf16.h>
#include <cstdint>

// ============================================================================
// CrossDepthAttention, mma.sync tensor cores (base-target legal).
//   P0: cur -> bf16; {Wq,Wv,Wo} -> bf16 (one launch); Wk -> transpose+bf16
//   K1: q    = cur @ Wq^T            bf16 BN=128, 3-stage cp.async
//   K2: qk_h = q_h @ Wk_h            bf16 persistent j-loop (dedicated stage)
//   K3: fused attention (2 barriers, multi-value butterfly) -> hbar bf16
//   K4: out_h = hbar_h @ Wv_h^T      bf16 BN=64, 2-stage -> out bf16
//   K5: final = cur + out @ Wo^T     bf16 BN=128, 3-stage + fp32 residual
// ============================================================================

#define D_DIM   1024
#define H_HEADS 16
#define HD      64
#define NPREV   8
#define M_MAX   8192

__device__ __nv_bfloat16 g_cb[M_MAX * D_DIM];                      // cur (bf16)
__device__ __nv_bfloat16 g_qb[M_MAX * D_DIM];                      // q (bf16)
__device__ __nv_bfloat16 g_qk[(size_t)M_MAX * H_HEADS * D_DIM];    // qk (bf16)
__device__ __nv_bfloat16 g_hb[(size_t)M_MAX * H_HEADS * D_DIM];    // hbar (bf16)
__device__ __nv_bfloat16 g_ob[M_MAX * D_DIM];                      // out (bf16)
__device__ __nv_bfloat16 g_wq[D_DIM * D_DIM];                      // Wq (bf16)
__device__ __nv_bfloat16 g_wkt[D_DIM * D_DIM];                     // Wk^T (bf16)
__device__ __nv_bfloat16 g_wv[D_DIM * D_DIM];                      // Wv (bf16)
__device__ __nv_bfloat16 g_wo[D_DIM * D_DIM];                      // Wo (bf16)

// ---------------------------------------------------------------------------
__device__ __forceinline__ uint32_t smem_u32(const void* p) {
    uint32_t a;
    asm("{ .reg .u64 t; cvta.to.shared.u64 t, %1; cvt.u32.u64 %0, t; }"
        : "=r"(a) : "l"(p));
    return a;
}
__device__ __forceinline__ void cp16(uint32_t s, const void* g) {
    asm volatile("cp.async.cg.shared.global [%0], [%1], 16;\n" :: "r"(s), "l"(g));
}
__device__ __forceinline__ void cp_commit() {
    asm volatile("cp.async.commit_group;\n" ::: "memory");
}
template <int N> __device__ __forceinline__ void cp_wait() {
    asm volatile("cp.async.wait_group %0;\n" :: "n"(N) : "memory");
}
__device__ __forceinline__ void mma_bf16(float* c, const uint32_t* a,
                                         const uint32_t* b) {
    asm volatile(
        "mma.sync.aligned.m16n8k16.row.col.f32.bf16.bf16.f32 "
        "{%0,%1,%2,%3}, {%4,%5,%6,%7}, {%8,%9}, {%0,%1,%2,%3};\n"
        : "+f"(c[0]), "+f"(c[1]), "+f"(c[2]), "+f"(c[3])
        : "r"(a[0]), "r"(a[1]), "r"(a[2]), "r"(a[3]), "r"(b[0]), "r"(b[1]));
}
__device__ __forceinline__ void ldsm_x4(uint32_t& r0, uint32_t& r1,
                                        uint32_t& r2, uint32_t& r3,
                                        uint32_t addr) {
    asm volatile("ldmatrix.sync.aligned.m8n8.x4.shared.b16 {%0,%1,%2,%3}, [%4];"
                 : "=r"(r0), "=r"(r1), "=r"(r2), "=r"(r3) : "r"(addr));
}
__device__ __forceinline__ uint32_t pack_bf162(float lo, float hi) {
    __nv_bfloat162 p = __float22bfloat162_rn(make_float2(lo, hi));
    return *reinterpret_cast<uint32_t*>(&p);
}

// ---------------------------------------------------------------------------
// P0a: Wk transpose + bf16 convert, tiled 32x32.
// ---------------------------------------------------------------------------
__global__ void __launch_bounds__(256) transpose_wk_bf16(
    const float* __restrict__ in, __nv_bfloat16* __restrict__ outp)
{
    __shared__ float t[32][33];
    const int bx = blockIdx.x * 32, by = blockIdx.y * 32;
    int x = bx + threadIdx.x;
#pragma unroll
    for (int i = 0; i < 32; i += 8)
        t[threadIdx.y + i][threadIdx.x] = in[(size_t)(by + threadIdx.y + i) * D_DIM + x];
    __syncthreads();
    x = by + threadIdx.x;
#pragma unroll
    for (int i = 0; i < 32; i += 8)
        outp[(size_t)(bx + threadIdx.y + i) * D_DIM + x] =
            __float2bfloat16(t[threadIdx.x][threadIdx.y + i]);
}

// P0b: fp32 -> bf16, single tensor (cur)
__global__ void __launch_bounds__(256) convert_f2b(
    const float* __restrict__ in, __nv_bfloat16* __restrict__ outp)
{
    int i = (blockIdx.x * 256 + threadIdx.x) * 4;
    float4 a = *(const float4*)(in + i);
    *(__nv_bfloat162*)(outp + i)     = __float22bfloat162_rn(make_float2(a.x, a.y));
    *(__nv_bfloat162*)(outp + i + 2) = __float22bfloat162_rn(make_float2(a.z, a.w));
}

// P0c: fp32 -> bf16 for three weight matrices in one launch
__global__ void __launch_bounds__(256) convert_w3(
    const float* __restrict__ w0, __nv_bfloat16* __restrict__ o0,
    const float* __restrict__ w1, __nv_bfloat16* __restrict__ o1,
    const float* __restrict__ w2, __nv_bfloat16* __restrict__ o2)
{
    const float* in;
    __nv_bfloat16* outp;
    if (blockIdx.y == 0)      { in = w0; outp = o0; }
    else if (blockIdx.y == 1) { in = w1; outp = o1; }
    else                      { in = w2; outp = o2; }
    int i = (blockIdx.x * 256 + threadIdx.x) * 4;
    float4 a = *(const float4*)(in + i);
    *(__nv_bfloat162*)(outp + i)     = __float22bfloat162_rn(make_float2(a.x, a.y));
    *(__nv_bfloat162*)(outp + i + 2) = __float22bfloat162_rn(make_float2(a.z, a.w));
}

// ---------------------------------------------------------------------------
// bf16 m16n8k16 GEMM (NT), ldmatrix loads, STAGES-deep cp.async pipeline.
//   C[m,n] = sum_k A[m,k] * B[n*ldb + k]; A,B bf16.
// CTA tile 128 x BN, BK=64 halves, 256 threads, stride 72 halves.
// Stage layout: stage s occupies [s*(A+B)] with A first, then B.
// OUT_BF16 epilogue staged through SMEM aliased onto (dead) stage 0.
// ---------------------------------------------------------------------------
template <int BN, int STAGES, bool OUT_BF16, bool RESID>
__global__ void __launch_bounds__(256)
gemm_bf16(const __nv_bfloat16* __restrict__ A, int lda, long long sA,
          const __nv_bfloat16* __restrict__ B, int ldb, long long sB,
          const float* __restrict__ R,
          void* __restrict__ C, int ldc, long long sC, int K)
{
    constexpr int WM = (BN == 128) ? 2 : 4;
    constexpr int MT = 8 / WM;
    constexpr int A_HALVES = 128 * 72;
    constexpr int B_HALVES = BN * 72;
    constexpr int S_HALVES = A_HALVES + B_HALVES;
    constexpr int STW = BN + 8;                    // stage stride (halves)

    extern __shared__ __align__(16) __nv_bfloat16 sm_h[];
    const uint32_t sbase = smem_u32(sm_h);

    const int tid = threadIdx.x;
    const int wid = tid >> 5, lane = tid & 31;
    const int wm = wid % WM, wn = wid / WM;
    const int bx = blockIdx.x, by = blockIdx.y, bz = blockIdx.z;

    const __nv_bfloat16* Ah = A + (long long)bz * sA + (size_t)(by * 128) * lda;
    const __nv_bfloat16* Bh = B + (long long)bz * sB + (size_t)(bx * BN) * ldb;

    auto fill = [&](int buf, int k0) {
        const uint32_t Ab = sbase + (uint32_t)(buf * S_HALVES) * 2u;
        const uint32_t Bb = sbase + (uint32_t)(buf * S_HALVES + A_HALVES) * 2u;
#pragma unroll
        for (int p = 0; p < 4; ++p) {
            int ch = tid + p * 256;
            int row = ch >> 3, c8 = ch & 7;
            cp16(Ab + (uint32_t)(row * 72 + c8 * 8) * 2u,
                 Ah + (size_t)row * lda + k0 + c8 * 8);
        }
#pragma unroll
        for (int p = 0; p < BN * 8 / 256; ++p) {
            int ch = tid + p * 256;
            int row = ch >> 3, c8 = ch & 7;
            cp16(Bb + (uint32_t)(row * 72 + c8 * 8) * 2u,
                 Bh + (size_t)row * ldb + k0 + c8 * 8);
        }
    };

    float acc[MT][4][4];
#pragma unroll
    for (int mt = 0; mt < MT; ++mt)
#pragma unroll
        for (int nt = 0; nt < 4; ++nt)
#pragma unroll
            for (int j = 0; j < 4; ++j) acc[mt][nt][j] = 0.0f;

    // ldmatrix lane address bases (in halves)
    const int r8 = lane & 7;
    const int a_base_h = (wm * (128 / WM) + ((lane >> 3) & 1) * 8 + r8) * 72
                       + ((lane >> 4) & 1) * 8;
    const int b_sel = (lane >> 3) & 3;
    const int b_base_h = (wn * 32 + (b_sel >> 1) * 8 + r8) * 72 + (b_sel & 1) * 8;

    const int NC = K / 64;
    // prologue: fill STAGES-1 stages
#pragma unroll
    for (int s = 0; s < STAGES - 1; ++s) {
        if (s < NC) { fill(s, s * 64); }
        cp_commit();
    }

    for (int c = 0; c < NC; ++c) {
        if (c + STAGES - 1 < NC) {
            fill((c + STAGES - 1) % STAGES, (c + STAGES - 1) * 64);
            cp_commit();
            cp_wait<STAGES - 1>();
        } else {
            cp_wait<0>();
        }
        __syncthreads();

        const int buf = c % STAGES;
        const uint32_t Ab = sbase + (uint32_t)(buf * S_HALVES) * 2u;
        const uint32_t Bb = sbase + (uint32_t)(buf * S_HALVES + A_HALVES) * 2u;

#pragma unroll
        for (int s = 0; s < 4; ++s) {
            uint32_t af[MT][4];
#pragma unroll
            for (int mt = 0; mt < MT; ++mt)
                ldsm_x4(af[mt][0], af[mt][1], af[mt][2], af[mt][3],
                        Ab + (uint32_t)(a_base_h + mt * 16 * 72 + s * 16) * 2u);
            uint32_t bfr[4][2];
#pragma unroll
            for (int ntp = 0; ntp < 2; ++ntp)
                ldsm_x4(bfr[2 * ntp][0], bfr[2 * ntp][1],
                        bfr[2 * ntp + 1][0], bfr[2 * ntp + 1][1],
                        Bb + (uint32_t)(b_base_h + ntp * 16 * 72 + s * 16) * 2u);
#pragma unroll
            for (int mt = 0; mt < MT; ++mt)
#pragma unroll
                for (int nt = 0; nt < 4; ++nt)
                    mma_bf16(acc[mt][nt], af[mt], bfr[nt]);
        }
        __syncthreads();
    }

    const int g = lane >> 2, tg = lane & 3;
    if (!OUT_BF16) {
        const int row0 = by * 128 + wm * (128 / WM) + g;
        const int coll = wn * 32 + tg * 2;
#pragma unroll
        for (int mt = 0; mt < MT; ++mt) {
            const int m = row0 + mt * 16;
#pragma unroll
            for (int nt = 0; nt < 4; ++nt) {
                const int n = bx * BN + coll + nt * 8;
                float* Cg = (float*)C + (long long)bz * sC;
                float2 v0 = make_float2(acc[mt][nt][0], acc[mt][nt][1]);
                float2 v1 = make_float2(acc[mt][nt][2], acc[mt][nt][3]);
                if (RESID) {
                    float2 r0 = *(const float2*)(R + (size_t)m * ldc + n);
                    float2 r1 = *(const float2*)(R + (size_t)(m + 8) * ldc + n);
                    v0.x += r0.x; v0.y += r0.y;
                    v1.x += r1.x; v1.y += r1.y;
                }
                *(float2*)(Cg + (size_t)m * ldc + n)       = v0;
                *(float2*)(Cg + (size_t)(m + 8) * ldc + n) = v1;
            }
        }
    } else {
        // staged epilogue ALIASED onto stage 0 (dead after last sync)
        __nv_bfloat16* stg = sm_h;
        const int ml0 = wm * (128 / WM) + g;
        const int nl0 = wn * 32 + tg * 2;
#pragma unroll
        for (int mt = 0; mt < MT; ++mt) {
            const int ml = ml0 + mt * 16;
#pragma unroll
            for (int nt = 0; nt < 4; ++nt) {
                const int nl = nl0 + nt * 8;
                *(uint32_t*)&stg[ml * STW + nl] =
                    pack_bf162(acc[mt][nt][0], acc[mt][nt][1]);
                *(uint32_t*)&stg[(ml + 8) * STW + nl] =
                    pack_bf162(acc[mt][nt][2], acc[mt][nt][3]);
            }
        }
        __syncthreads();
        __nv_bfloat16* Cg = (__nv_bfloat16*)C + (long long)bz * sC;
#pragma unroll
        for (int p = 0; p < 128 * BN / 8 / 256; ++p) {
            int ch = tid + p * 256;
            int row = ch / (BN / 8), c8 = ch % (BN / 8);
            uint4 v = *(uint4*)&stg[row * STW + c8 * 8];
            *(uint4*)(Cg + (size_t)(by * 128 + row) * ldc + bx * BN + c8 * 8) = v;
        }
    }
}

// ---------------------------------------------------------------------------
// K2: persistent j-loop bf16 GEMM, ldmatrix, dedicated SMEM stage.
//   qk[m, h*1024 + j] = sum_d q[m, h*64+d] * wkt[j, h*64+d]
// ---------------------------------------------------------------------------
__global__ void __launch_bounds__(256)
gemm_k2(const __nv_bfloat16* __restrict__ Q,
        const __nv_bfloat16* __restrict__ WKT,
        __nv_bfloat16* __restrict__ QK)
{
    constexpr int A_HALVES = 128 * 72;
    constexpr int B_HALVES = 128 * 72;
    constexpr int STW = 136;                       // stage stride (halves)

    extern __shared__ __align__(16) __nv_bfloat16 sm_h[];
    const uint32_t sbase = smem_u32(sm_h);

    const int tid = threadIdx.x;
    const int wid = tid >> 5, lane = tid & 31;
    const int wm = wid & 1, wn = wid >> 1;
    const int by = blockIdx.x;           // m-tile
    const int h  = blockIdx.y;           // head

    const __nv_bfloat16* Ah = Q + (size_t)(by * 128) * D_DIM + h * HD;
    const __nv_bfloat16* Bh = WKT + h * HD;

    // A: 128 rows x 64 halves = 1024 chunks of 16B (4 per thread)
#pragma unroll
    for (int p = 0; p < 4; ++p) {
        int ch = tid + p * 256;
        int row = ch >> 3, c8 = ch & 7;
        cp16(sbase + (uint32_t)(row * 72 + c8 * 8) * 2u,
             Ah + (size_t)row * D_DIM + c8 * 8);
    }
    auto fillB = [&](int buf, int j0) {
        const uint32_t Bb = sbase + (uint32_t)(A_HALVES + buf * B_HALVES) * 2u;
#pragma unroll
        for (int p = 0; p < 4; ++p) {
            int ch = tid + p * 256;
            int row = ch >> 3, c8 = ch & 7;
            cp16(Bb + (uint32_t)(row * 72 + c8 * 8) * 2u,
                 Bh + (size_t)(j0 + row) * D_DIM + c8 * 8);
        }
    };
    fillB(0, 0);
    cp_commit();        // group 0: A + B0

    // ldmatrix bases
    const int r8 = lane & 7;
    const int a_base_h = (wm * 64 + ((lane >> 3) & 1) * 8 + r8) * 72
                       + ((lane >> 4) & 1) * 8;
    const int b_sel = (lane >> 3) & 3;
    const int b_base_h = (wn * 32 + (b_sel >> 1) * 8 + r8) * 72 + (b_sel & 1) * 8;

    const int g = lane >> 2, tg = lane & 3;
    __nv_bfloat16* stg = sm_h + A_HALVES + 2 * B_HALVES;

    for (int jt = 0; jt < 8; ++jt) {
        if (jt + 1 < 8) { fillB((jt + 1) & 1, (jt + 1) * 128); cp_commit(); cp_wait<1>(); }
        else            { cp_wait<0>(); }
        __syncthreads();

        const uint32_t Bb = sbase + (uint32_t)(A_HALVES + (jt & 1) * B_HALVES) * 2u;

        float acc[4][4][4];
#pragma unroll
        for (int mt = 0; mt < 4; ++mt)
#pragma unroll
            for (int nt = 0; nt < 4; ++nt)
#pragma unroll
                for (int j = 0; j < 4; ++j) acc[mt][nt][j] = 0.0f;

#pragma unroll
        for (int s = 0; s < 4; ++s) {              // 4 x k16 over K=64
            uint32_t af[4][4];
#pragma unroll
            for (int mt = 0; mt < 4; ++mt)
                ldsm_x4(af[mt][0], af[mt][1], af[mt][2], af[mt][3],
                        sbase + (uint32_t)(a_base_h + mt * 16 * 72 + s * 16) * 2u);
            uint32_t bfr[4][2];
#pragma unroll
            for (int ntp = 0; ntp < 2; ++ntp)
                ldsm_x4(bfr[2 * ntp][0], bfr[2 * ntp][1],
                        bfr[2 * ntp + 1][0], bfr[2 * ntp + 1][1],
                        Bb + (uint32_t)(b_base_h + ntp * 16 * 72 + s * 16) * 2u);
#pragma unroll
            for (int mt = 0; mt < 4; ++mt)
#pragma unroll
                for (int nt = 0; nt < 4; ++nt)
                    mma_bf16(acc[mt][nt], af[mt], bfr[nt]);
        }

        // staged epilogue for this j-tile
        const int ml0 = wm * 64 + g;
        const int nl0 = wn * 32 + tg * 2;
#pragma unroll
        for (int mt = 0; mt < 4; ++mt) {
            const int ml = ml0 + mt * 16;
#pragma unroll
            for (int nt = 0; nt < 4; ++nt) {
                const int nl = nl0 + nt * 8;
                *(uint32_t*)&stg[ml * STW + nl] =
                    pack_bf162(acc[mt][nt][0], acc[mt][nt][1]);
                *(uint32_t*)&stg[(ml + 8) * STW + nl] =
                    pack_bf162(acc[mt][nt][2], acc[mt][nt][3]);
            }
        }
        __syncthreads();
        __nv_bfloat16* Cg = QK + (size_t)h * D_DIM + (size_t)jt * 128;
#pragma unroll
        for (int p = 0; p < 8; ++p) {
            int ch = tid + p * 256;
            int row = ch >> 4, c8 = ch & 15;
            uint4 v = *(uint4*)&stg[row * STW + c8 * 8];
            *(uint4*)(Cg + (size_t)(by * 128 + row) * (H_HEADS * D_DIM) + c8 * 8) = v;
        }
    }
}

// ---------------------------------------------------------------------------
// K3: fused attention — 2 barriers + multi-value butterfly. hbar -> bf16.
// ---------------------------------------------------------------------------
__global__ void __launch_bounds__(256) attn_kernel(
    const float* __restrict__ hist, const __nv_bfloat16* __restrict__ qk,
    __nv_bfloat16* __restrict__ hbar)
{
    __shared__ float red[H_HEADS][NPREV][8];
    __shared__ __align__(16) float attn_s[H_HEADS][NPREV];

    const int m    = blockIdx.x;
    const int tid  = threadIdx.x;
    const int lane = tid & 31;
    const int warp = tid >> 5;

    const __nv_bfloat16* qrow = qk + (size_t)m * (H_HEADS * D_DIM) + tid * 4;
    uint2 q2[H_HEADS];
#pragma unroll
    for (int h = 0; h < H_HEADS; h++)
        q2[h] = *(const uint2*)(qrow + h * D_DIM);

    float4 hv[NPREV];
    const float* hg = hist + (size_t)m * NPREV * D_DIM + tid * 4;
#pragma unroll
    for (int n = 0; n < NPREV; n++)
        hv[n] = *(const float4*)(hg + n * D_DIM);

    // ---- Phase A: dots + multi-value butterfly reduction ----
#pragma unroll
    for (int h = 0; h < H_HEADS; h++) {
        float2 qa = __bfloat1622float2(*reinterpret_cast<__nv_bfloat162*>(&q2[h].x));
        float2 qb = __bfloat1622float2(*reinterpret_cast<__nv_bfloat162*>(&q2[h].y));
        float p[NPREV];
#pragma unroll
        for (int n = 0; n < NPREV; n++)
            p[n] = qa.x * hv[n].x + qa.y * hv[n].y
                 + qb.x * hv[n].z + qb.y * hv[n].w;

#pragma unroll
        for (int i = 0; i < 4; i++) {
            float send = (lane & 16) ? p[i] : p[i + 4];
            float recv = __shfl_xor_sync(0xffffffffu, send, 16);
            p[i] = ((lane & 16) ? p[i + 4] : p[i]) + recv;
        }
#pragma unroll
        for (int i = 0; i < 2; i++) {
            float send = (lane & 8) ? p[i] : p[i + 2];
            float recv = __shfl_xor_sync(0xffffffffu, send, 8);
            p[i] = ((lane & 8) ? p[i + 2] : p[i]) + recv;
        }
        {
            float send = (lane & 4) ? p[0] : p[1];
            float recv = __shfl_xor_sync(0xffffffffu, send, 4);
            p[0] = ((lane & 4) ? p[1] : p[0]) + recv;
        }
        p[0] += __shfl_xor_sync(0xffffffffu, p[0], 2);
        p[0] += __shfl_xor_sync(0xffffffffu, p[0], 1);
        if ((lane & 3) == 0) red[h][lane >> 2][warp] = p[0];
    }
    __syncthreads();

    // ---- Phase B: 16 parallel softmaxes ----
    if (tid < H_HEADS) {
        const int h = tid;
        float lg[NPREV];
        float mx = -1e30f;
#pragma unroll
        for (int n = 0; n < NPREV; n++) {
            float4 s0 = *(const float4*)&red[h][n][0];
            float4 s1 = *(const float4*)&red[h][n][4];
            float s = (s0.x + s0.y) + (s0.z + s0.w)
                    + (s1.x + s1.y) + (s1.z + s1.w);
            lg[n] = s * 0.125f;
            mx = fmaxf(mx, lg[n]);
        }
        float den = 0.0f;
#pragma unroll
        for (int n = 0; n < NPREV; n++) { lg[n] = expf(lg[n] - mx); den += lg[n]; }
        float inv = 1.0f / den;
#pragma unroll
        for (int n = 0; n < NPREV; n++) attn_s[h][n] = lg[n] * inv;
    }
    __syncthreads();

    // ---- Phase C: weighted sums + bf16 stores ----
    __nv_bfloat16* orow = hbar + (size_t)m * (H_HEADS * D_DIM) + tid * 4;
#pragma unroll
    for (int h = 0; h < H_HEADS; h++) {
        float4 w0 = *(const float4*)&attn_s[h][0];
        float4 w1 = *(const float4*)&attn_s[h][4];
        float4 a4;
        a4.x = w0.x * hv[0].x; a4.y = w0.x * hv[0].y;
        a4.z = w0.x * hv[0].z; a4.w = w0.x * hv[0].w;
        a4.x = fmaf(w0.y, hv[1].x, a4.x); a4.y = fmaf(w0.y, hv[1].y, a4.y);
        a4.z = fmaf(w0.y, hv[1].z, a4.z); a4.w = fmaf(w0.y, hv[1].w, a4.w);
        a4.x = fmaf(w0.z, hv[2].x, a4.x); a4.y = fmaf(w0.z, hv[2].y, a4.y);
        a4.z = fmaf(w0.z, hv[2].z, a4.z); a4.w = fmaf(w0.z, hv[2].w, a4.w);
        a4.x = fmaf(w0.w, hv[3].x, a4.x); a4.y = fmaf(w0.w, hv[3].y, a4.y);
        a4.z = fmaf(w0.w, hv[3].z, a4.z); a4.w = fmaf(w0.w, hv[3].w, a4.w);
        a4.x = fmaf(w1.x, hv[4].x, a4.x); a4.y = fmaf(w1.x, hv[4].y, a4.y);
        a4.z = fmaf(w1.x, hv[4].z, a4.z); a4.w = fmaf(w1.x, hv[4].w, a4.w);
        a4.x = fmaf(w1.y, hv[5].x, a4.x); a4.y = fmaf(w1.y, hv[5].y, a4.y);
        a4.z = fmaf(w1.y, hv[5].z, a4.z); a4.w = fmaf(w1.y, hv[5].w, a4.w);
        a4.x = fmaf(w1.z, hv[6].x, a4.x); a4.y = fmaf(w1.z, hv[6].y, a4.y);
        a4.z = fmaf(w1.z, hv[6].z, a4.z); a4.w = fmaf(w1.z, hv[6].w, a4.w);
        a4.x = fmaf(w1.w, hv[7].x, a4.x); a4.y = fmaf(w1.w, hv[7].y, a4.y);
        a4.z = fmaf(w1.w, hv[7].z, a4.z); a4.w = fmaf(w1.w, hv[7].w, a4.w);
        uint2 ov;
        ov.x = pack_bf162(a4.x, a4.y);
        ov.y = pack_bf162(a4.z, a4.w);
        *(uint2*)(orow + h * D_DIM) = ov;
    }
}

// ---------------------------------------------------------------------------
extern "C" void kernel_launch(void* const* d_in, const int* in_sizes, int n_in,
                              void* d_out, int out_size)
{
    const float* cur  = (const float*)d_in[0];
    const float* hist = (const float*)d_in[1];
    const float* Wq   = (const float*)d_in[2];
    const float* Wk   = (const float*)d_in[3];
    const float* Wv   = (const float*)d_in[4];
    const float* Wo   = (const float*)d_in[5];
    float* out = (float*)d_out;

    const int D = D_DIM;
    const int M = in_sizes[0] / D;   // 8192

    __nv_bfloat16 *cb = nullptr, *qb = nullptr, *qk = nullptr, *hb = nullptr;
    __nv_bfloat16 *ob = nullptr, *wq = nullptr, *wkt = nullptr, *wv = nullptr, *wo = nullptr;
    cudaGetSymbolAddress((void**)&cb,  g_cb);
    cudaGetSymbolAddress((void**)&qb,  g_qb);
    cudaGetSymbolAddress((void**)&qk,  g_qk);
    cudaGetSymbolAddress((void**)&hb,  g_hb);
    cudaGetSymbolAddress((void**)&ob,  g_ob);
    cudaGetSymbolAddress((void**)&wq,  g_wq);
    cudaGetSymbolAddress((void**)&wkt, g_wkt);
    cudaGetSymbolAddress((void**)&wv,  g_wv);
    cudaGetSymbolAddress((void**)&wo,  g_wo);

    // SMEM budgets (bytes)
    constexpr int SM_K2    = (128 * 72 + 2 * (128 * 72) + 128 * 136) * 2;  // 90112
    constexpr int SM_B64   = 2 * (128 * 72 + 64 * 72) * 2;                 // 55296
    constexpr int SM_B128T = 3 * (128 * 72 + 128 * 72) * 2;                // 110592

    cudaFuncSetAttribute(gemm_k2,
                         cudaFuncAttributeMaxDynamicSharedMemorySize, SM_K2);
    cudaFuncSetAttribute(gemm_bf16<64, 2, true, false>,
                         cudaFuncAttributeMaxDynamicSharedMemorySize, SM_B64);
    cudaFuncSetAttribute(gemm_bf16<128, 3, true, false>,
                         cudaFuncAttributeMaxDynamicSharedMemorySize, SM_B128T);
    cudaFuncSetAttribute(gemm_bf16<128, 3, false, true>,
                         cudaFuncAttributeMaxDynamicSharedMemorySize, SM_B128T);

    // P0: conversions
    convert_f2b<<<M * D / 4 / 256, 256>>>(cur, cb);
    convert_w3<<<dim3(D * D / 4 / 256, 3), 256>>>(Wq, wq, Wv, wv, Wo, wo);
    transpose_wk_bf16<<<dim3(32, 32), dim3(32, 8)>>>(Wk, wkt);

    // K1: q = cur @ Wq^T  (bf16, BN=128, 3-stage) -> bf16
    gemm_bf16<128, 3, true, false>
        <<<dim3(D / 128, M / 128, 1), 256, SM_B128T>>>(
            cb, D, 0, wq, D, 0, nullptr, qb, D, 0, D);

    // K2: qk_h = q_h @ Wk_h  (bf16, persistent j-loop, staged) -> bf16
    gemm_k2<<<dim3(M / 128, H_HEADS), 256, SM_K2>>>(qb, wkt, qk);

    // K3: attention -> hbar (bf16)
    attn_kernel<<<M, 256>>>(hist, qk, hb);

    // K4: out_h = hbar_h @ Wv_h^T (bf16, BN=64, 2-stage) -> out bf16
    gemm_bf16<64, 2, true, false>
        <<<dim3(1, M / 128, H_HEADS), 256, SM_B64>>>(
            hb, H_HEADS * D, D,
            wv, D, (long long)HD * D,
            nullptr,
            ob, D, HD,
            D);

    // K5: final = cur + out @ Wo^T  (bf16, BN=128, 3-stage + fp32 residual)
    gemm_bf16<128, 3, false, true>
        <<<dim3(D / 128, M / 128, 1), 256, SM_B128T>>>(
            ob, D, 0, wo, D, 0, cur, out, D, 0, D);
}

// round 17
// speedup vs baseline: 1.4675x; 1.0179x over previous
#include <cuda_runtime.h>
#include <cuda_bf16.h>
#include <cstdint>

// ============================================================================
// CrossDepthAttention, mma.sync tensor cores (base-target legal).
//   P0: one fused conversion kernel (cur,Wq,Wv,Wo -> bf16) + Wk transpose
//   K1: q    = cur @ Wq^T            bf16 BN=128, 2-stage (proven R14 config)
//   K2: qk_h = q_h @ Wk_h            bf16 persistent j-loop (dedicated stage)
//   K3: fused attention (2 barriers, multi-value butterfly) -> hbar bf16
//   K4: out_h = hbar_h @ Wv_h^T      bf16 BN=64 -> out bf16
//   K5: final = cur + out @ Wo^T     bf16 BN=128 + fp32 residual
// ============================================================================

#define D_DIM   1024
#define H_HEADS 16
#define HD      64
#define NPREV   8
#define M_MAX   8192

__device__ __nv_bfloat16 g_cb[M_MAX * D_DIM];                      // cur (bf16)
__device__ __nv_bfloat16 g_qb[M_MAX * D_DIM];                      // q (bf16)
__device__ __nv_bfloat16 g_qk[(size_t)M_MAX * H_HEADS * D_DIM];    // qk (bf16)
__device__ __nv_bfloat16 g_hb[(size_t)M_MAX * H_HEADS * D_DIM];    // hbar (bf16)
__device__ __nv_bfloat16 g_ob[M_MAX * D_DIM];                      // out (bf16)
__device__ __nv_bfloat16 g_wq[D_DIM * D_DIM];                      // Wq (bf16)
__device__ __nv_bfloat16 g_wkt[D_DIM * D_DIM];                     // Wk^T (bf16)
__device__ __nv_bfloat16 g_wv[D_DIM * D_DIM];                      // Wv (bf16)
__device__ __nv_bfloat16 g_wo[D_DIM * D_DIM];                      // Wo (bf16)

// ---------------------------------------------------------------------------
__device__ __forceinline__ uint32_t smem_u32(const void* p) {
    uint32_t a;
    asm("{ .reg .u64 t; cvta.to.shared.u64 t, %1; cvt.u32.u64 %0, t; }"
        : "=r"(a) : "l"(p));
    return a;
}
__device__ __forceinline__ void cp16(uint32_t s, const void* g) {
    asm volatile("cp.async.cg.shared.global [%0], [%1], 16;\n" :: "r"(s), "l"(g));
}
__device__ __forceinline__ void cp_commit() {
    asm volatile("cp.async.commit_group;\n" ::: "memory");
}
template <int N> __device__ __forceinline__ void cp_wait() {
    asm volatile("cp.async.wait_group %0;\n" :: "n"(N) : "memory");
}
__device__ __forceinline__ void mma_bf16(float* c, const uint32_t* a,
                                         const uint32_t* b) {
    asm volatile(
        "mma.sync.aligned.m16n8k16.row.col.f32.bf16.bf16.f32 "
        "{%0,%1,%2,%3}, {%4,%5,%6,%7}, {%8,%9}, {%0,%1,%2,%3};\n"
        : "+f"(c[0]), "+f"(c[1]), "+f"(c[2]), "+f"(c[3])
        : "r"(a[0]), "r"(a[1]), "r"(a[2]), "r"(a[3]), "r"(b[0]), "r"(b[1]));
}
__device__ __forceinline__ void ldsm_x4(uint32_t& r0, uint32_t& r1,
                                        uint32_t& r2, uint32_t& r3,
                                        uint32_t addr) {
    asm volatile("ldmatrix.sync.aligned.m8n8.x4.shared.b16 {%0,%1,%2,%3}, [%4];"
                 : "=r"(r0), "=r"(r1), "=r"(r2), "=r"(r3) : "r"(addr));
}
__device__ __forceinline__ uint32_t pack_bf162(float lo, float hi) {
    __nv_bfloat162 p = __float22bfloat162_rn(make_float2(lo, hi));
    return *reinterpret_cast<uint32_t*>(&p);
}

// ---------------------------------------------------------------------------
// P0a: Wk transpose + bf16 convert, tiled 32x32.
// ---------------------------------------------------------------------------
__global__ void __launch_bounds__(256) transpose_wk_bf16(
    const float* __restrict__ in, __nv_bfloat16* __restrict__ outp)
{
    __shared__ float t[32][33];
    const int bx = blockIdx.x * 32, by = blockIdx.y * 32;
    int x = bx + threadIdx.x;
#pragma unroll
    for (int i = 0; i < 32; i += 8)
        t[threadIdx.y + i][threadIdx.x] = in[(size_t)(by + threadIdx.y + i) * D_DIM + x];
    __syncthreads();
    x = by + threadIdx.x;
#pragma unroll
    for (int i = 0; i < 32; i += 8)
        outp[(size_t)(bx + threadIdx.y + i) * D_DIM + x] =
            __float2bfloat16(t[threadIdx.x][threadIdx.y + i]);
}

// P0b: fused fp32 -> bf16 conversion for cur + Wq + Wv + Wo (one launch).
// Block index space: [0, NB_CUR) -> cur; then NB_W each for Wq, Wv, Wo.
__global__ void __launch_bounds__(256) convert_all(
    const float* __restrict__ cur, __nv_bfloat16* __restrict__ cb,
    const float* __restrict__ wq,  __nv_bfloat16* __restrict__ oq,
    const float* __restrict__ wv,  __nv_bfloat16* __restrict__ ov,
    const float* __restrict__ wo,  __nv_bfloat16* __restrict__ oo,
    int nb_cur, int nb_w)
{
    const float* in;
    __nv_bfloat16* outp;
    int b = blockIdx.x;
    if (b < nb_cur)                 { in = cur; outp = cb; }
    else if (b < nb_cur + nb_w)     { in = wq;  outp = oq; b -= nb_cur; }
    else if (b < nb_cur + 2 * nb_w) { in = wv;  outp = ov; b -= nb_cur + nb_w; }
    else                            { in = wo;  outp = oo; b -= nb_cur + 2 * nb_w; }
    int i = (b * 256 + threadIdx.x) * 4;
    float4 a = *(const float4*)(in + i);
    *(__nv_bfloat162*)(outp + i)     = __float22bfloat162_rn(make_float2(a.x, a.y));
    *(__nv_bfloat162*)(outp + i + 2) = __float22bfloat162_rn(make_float2(a.z, a.w));
}

// ---------------------------------------------------------------------------
// bf16 m16n8k16 GEMM (NT), ldmatrix loads, double-buffered cp.async.
//   C[m,n] = sum_k A[m,k] * B[n*ldb + k]; A,B bf16.
// CTA tile 128 x BN, BK=64 halves, 256 threads, stride 72 halves.
// OUT_BF16 epilogue staged through SMEM aliased onto (dead) mainloop buffers.
// ---------------------------------------------------------------------------
template <int BN, bool OUT_BF16, bool RESID>
__global__ void __launch_bounds__(256)
gemm_bf16(const __nv_bfloat16* __restrict__ A, int lda, long long sA,
          const __nv_bfloat16* __restrict__ B, int ldb, long long sB,
          const float* __restrict__ R,
          void* __restrict__ C, int ldc, long long sC, int K)
{
    constexpr int WM = (BN == 128) ? 2 : 4;
    constexpr int MT = 8 / WM;
    constexpr int A_HALVES = 128 * 72;
    constexpr int B_HALVES = BN * 72;
    constexpr int STW = BN + 8;                    // stage stride (halves)

    extern __shared__ __align__(16) __nv_bfloat16 sm_h[];
    const uint32_t sbase = smem_u32(sm_h);

    const int tid = threadIdx.x;
    const int wid = tid >> 5, lane = tid & 31;
    const int wm = wid % WM, wn = wid / WM;
    const int bx = blockIdx.x, by = blockIdx.y, bz = blockIdx.z;

    const __nv_bfloat16* Ah = A + (long long)bz * sA + (size_t)(by * 128) * lda;
    const __nv_bfloat16* Bh = B + (long long)bz * sB + (size_t)(bx * BN) * ldb;

    auto fill = [&](int buf, int k0) {
        const uint32_t Ab = sbase + (uint32_t)(buf * A_HALVES) * 2u;
        const uint32_t Bb = sbase + (uint32_t)(2 * A_HALVES + buf * B_HALVES) * 2u;
#pragma unroll
        for (int p = 0; p < 4; ++p) {
            int ch = tid + p * 256;
            int row = ch >> 3, c8 = ch & 7;
            cp16(Ab + (uint32_t)(row * 72 + c8 * 8) * 2u,
                 Ah + (size_t)row * lda + k0 + c8 * 8);
        }
#pragma unroll
        for (int p = 0; p < BN * 8 / 256; ++p) {
            int ch = tid + p * 256;
            int row = ch >> 3, c8 = ch & 7;
            cp16(Bb + (uint32_t)(row * 72 + c8 * 8) * 2u,
                 Bh + (size_t)row * ldb + k0 + c8 * 8);
        }
    };

    float acc[MT][4][4];
#pragma unroll
    for (int mt = 0; mt < MT; ++mt)
#pragma unroll
        for (int nt = 0; nt < 4; ++nt)
#pragma unroll
            for (int j = 0; j < 4; ++j) acc[mt][nt][j] = 0.0f;

    // ldmatrix lane address bases (in halves)
    const int r8 = lane & 7;
    const int a_base_h = (wm * (128 / WM) + ((lane >> 3) & 1) * 8 + r8) * 72
                       + ((lane >> 4) & 1) * 8;
    const int b_sel = (lane >> 3) & 3;
    const int b_base_h = (wn * 32 + (b_sel >> 1) * 8 + r8) * 72 + (b_sel & 1) * 8;

    const int NC = K / 64;
    fill(0, 0);
    cp_commit();

    for (int c = 0; c < NC; ++c) {
        if (c + 1 < NC) { fill((c + 1) & 1, (c + 1) * 64); cp_commit(); cp_wait<1>(); }
        else            { cp_wait<0>(); }
        __syncthreads();

        const int buf = c & 1;
        const uint32_t Ab = sbase + (uint32_t)(buf * A_HALVES) * 2u;
        const uint32_t Bb = sbase + (uint32_t)(2 * A_HALVES + buf * B_HALVES) * 2u;

#pragma unroll
        for (int s = 0; s < 4; ++s) {
            uint32_t af[MT][4];
#pragma unroll
            for (int mt = 0; mt < MT; ++mt)
                ldsm_x4(af[mt][0], af[mt][1], af[mt][2], af[mt][3],
                        Ab + (uint32_t)(a_base_h + mt * 16 * 72 + s * 16) * 2u);
            uint32_t bfr[4][2];
#pragma unroll
            for (int ntp = 0; ntp < 2; ++ntp)
                ldsm_x4(bfr[2 * ntp][0], bfr[2 * ntp][1],
                        bfr[2 * ntp + 1][0], bfr[2 * ntp + 1][1],
                        Bb + (uint32_t)(b_base_h + ntp * 16 * 72 + s * 16) * 2u);
#pragma unroll
            for (int mt = 0; mt < MT; ++mt)
#pragma unroll
                for (int nt = 0; nt < 4; ++nt)
                    mma_bf16(acc[mt][nt], af[mt], bfr[nt]);
        }
        __syncthreads();
    }

    const int g = lane >> 2, tg = lane & 3;
    if (!OUT_BF16) {
        const int row0 = by * 128 + wm * (128 / WM) + g;
        const int coll = wn * 32 + tg * 2;
#pragma unroll
        for (int mt = 0; mt < MT; ++mt) {
            const int m = row0 + mt * 16;
#pragma unroll
            for (int nt = 0; nt < 4; ++nt) {
                const int n = bx * BN + coll + nt * 8;
                float* Cg = (float*)C + (long long)bz * sC;
                float2 v0 = make_float2(acc[mt][nt][0], acc[mt][nt][1]);
                float2 v1 = make_float2(acc[mt][nt][2], acc[mt][nt][3]);
                if (RESID) {
                    float2 r0 = *(const float2*)(R + (size_t)m * ldc + n);
                    float2 r1 = *(const float2*)(R + (size_t)(m + 8) * ldc + n);
                    v0.x += r0.x; v0.y += r0.y;
                    v1.x += r1.x; v1.y += r1.y;
                }
                *(float2*)(Cg + (size_t)m * ldc + n)       = v0;
                *(float2*)(Cg + (size_t)(m + 8) * ldc + n) = v1;
            }
        }
    } else {
        // staged epilogue ALIASED onto mainloop buffers (dead after last sync)
        __nv_bfloat16* stg = sm_h;
        const int ml0 = wm * (128 / WM) + g;
        const int nl0 = wn * 32 + tg * 2;
#pragma unroll
        for (int mt = 0; mt < MT; ++mt) {
            const int ml = ml0 + mt * 16;
#pragma unroll
            for (int nt = 0; nt < 4; ++nt) {
                const int nl = nl0 + nt * 8;
                *(uint32_t*)&stg[ml * STW + nl] =
                    pack_bf162(acc[mt][nt][0], acc[mt][nt][1]);
                *(uint32_t*)&stg[(ml + 8) * STW + nl] =
                    pack_bf162(acc[mt][nt][2], acc[mt][nt][3]);
            }
        }
        __syncthreads();
        __nv_bfloat16* Cg = (__nv_bfloat16*)C + (long long)bz * sC;
#pragma unroll
        for (int p = 0; p < 128 * BN / 8 / 256; ++p) {
            int ch = tid + p * 256;
            int row = ch / (BN / 8), c8 = ch % (BN / 8);
            uint4 v = *(uint4*)&stg[row * STW + c8 * 8];
            *(uint4*)(Cg + (size_t)(by * 128 + row) * ldc + bx * BN + c8 * 8) = v;
        }
    }
}

// ---------------------------------------------------------------------------
// K2: persistent j-loop bf16 GEMM, ldmatrix, dedicated SMEM stage.
//   qk[m, h*1024 + j] = sum_d q[m, h*64+d] * wkt[j, h*64+d]
// ---------------------------------------------------------------------------
__global__ void __launch_bounds__(256)
gemm_k2(const __nv_bfloat16* __restrict__ Q,
        const __nv_bfloat16* __restrict__ WKT,
        __nv_bfloat16* __restrict__ QK)
{
    constexpr int A_HALVES = 128 * 72;
    constexpr int B_HALVES = 128 * 72;
    constexpr int STW = 136;                       // stage stride (halves)

    extern __shared__ __align__(16) __nv_bfloat16 sm_h[];
    const uint32_t sbase = smem_u32(sm_h);

    const int tid = threadIdx.x;
    const int wid = tid >> 5, lane = tid & 31;
    const int wm = wid & 1, wn = wid >> 1;
    const int by = blockIdx.x;           // m-tile
    const int h  = blockIdx.y;           // head

    const __nv_bfloat16* Ah = Q + (size_t)(by * 128) * D_DIM + h * HD;
    const __nv_bfloat16* Bh = WKT + h * HD;

    // A: 128 rows x 64 halves = 1024 chunks of 16B (4 per thread)
#pragma unroll
    for (int p = 0; p < 4; ++p) {
        int ch = tid + p * 256;
        int row = ch >> 3, c8 = ch & 7;
        cp16(sbase + (uint32_t)(row * 72 + c8 * 8) * 2u,
             Ah + (size_t)row * D_DIM + c8 * 8);
    }
    auto fillB = [&](int buf, int j0) {
        const uint32_t Bb = sbase + (uint32_t)(A_HALVES + buf * B_HALVES) * 2u;
#pragma unroll
        for (int p = 0; p < 4; ++p) {
            int ch = tid + p * 256;
            int row = ch >> 3, c8 = ch & 7;
            cp16(Bb + (uint32_t)(row * 72 + c8 * 8) * 2u,
                 Bh + (size_t)(j0 + row) * D_DIM + c8 * 8);
        }
    };
    fillB(0, 0);
    cp_commit();        // group 0: A + B0

    // ldmatrix bases
    const int r8 = lane & 7;
    const int a_base_h = (wm * 64 + ((lane >> 3) & 1) * 8 + r8) * 72
                       + ((lane >> 4) & 1) * 8;
    const int b_sel = (lane >> 3) & 3;
    const int b_base_h = (wn * 32 + (b_sel >> 1) * 8 + r8) * 72 + (b_sel & 1) * 8;

    const int g = lane >> 2, tg = lane & 3;
    __nv_bfloat16* stg = sm_h + A_HALVES + 2 * B_HALVES;

    for (int jt = 0; jt < 8; ++jt) {
        if (jt + 1 < 8) { fillB((jt + 1) & 1, (jt + 1) * 128); cp_commit(); cp_wait<1>(); }
        else            { cp_wait<0>(); }
        __syncthreads();

        const uint32_t Bb = sbase + (uint32_t)(A_HALVES + (jt & 1) * B_HALVES) * 2u;

        float acc[4][4][4];
#pragma unroll
        for (int mt = 0; mt < 4; ++mt)
#pragma unroll
            for (int nt = 0; nt < 4; ++nt)
#pragma unroll
                for (int j = 0; j < 4; ++j) acc[mt][nt][j] = 0.0f;

#pragma unroll
        for (int s = 0; s < 4; ++s) {              // 4 x k16 over K=64
            uint32_t af[4][4];
#pragma unroll
            for (int mt = 0; mt < 4; ++mt)
                ldsm_x4(af[mt][0], af[mt][1], af[mt][2], af[mt][3],
                        sbase + (uint32_t)(a_base_h + mt * 16 * 72 + s * 16) * 2u);
            uint32_t bfr[4][2];
#pragma unroll
            for (int ntp = 0; ntp < 2; ++ntp)
                ldsm_x4(bfr[2 * ntp][0], bfr[2 * ntp][1],
                        bfr[2 * ntp + 1][0], bfr[2 * ntp + 1][1],
                        Bb + (uint32_t)(b_base_h + ntp * 16 * 72 + s * 16) * 2u);
#pragma unroll
            for (int mt = 0; mt < 4; ++mt)
#pragma unroll
                for (int nt = 0; nt < 4; ++nt)
                    mma_bf16(acc[mt][nt], af[mt], bfr[nt]);
        }

        // staged epilogue for this j-tile
        const int ml0 = wm * 64 + g;
        const int nl0 = wn * 32 + tg * 2;
#pragma unroll
        for (int mt = 0; mt < 4; ++mt) {
            const int ml = ml0 + mt * 16;
#pragma unroll
            for (int nt = 0; nt < 4; ++nt) {
                const int nl = nl0 + nt * 8;
                *(uint32_t*)&stg[ml * STW + nl] =
                    pack_bf162(acc[mt][nt][0], acc[mt][nt][1]);
                *(uint32_t*)&stg[(ml + 8) * STW + nl] =
                    pack_bf162(acc[mt][nt][2], acc[mt][nt][3]);
            }
        }
        __syncthreads();
        __nv_bfloat16* Cg = QK + (size_t)h * D_DIM + (size_t)jt * 128;
#pragma unroll
        for (int p = 0; p < 8; ++p) {
            int ch = tid + p * 256;
            int row = ch >> 4, c8 = ch & 15;
            uint4 v = *(uint4*)&stg[row * STW + c8 * 8];
            *(uint4*)(Cg + (size_t)(by * 128 + row) * (H_HEADS * D_DIM) + c8 * 8) = v;
        }
    }
}

// ---------------------------------------------------------------------------
// K3: fused attention — 2 barriers + multi-value butterfly. hbar -> bf16.
// ---------------------------------------------------------------------------
__global__ void __launch_bounds__(256) attn_kernel(
    const float* __restrict__ hist, const __nv_bfloat16* __restrict__ qk,
    __nv_bfloat16* __restrict__ hbar)
{
    __shared__ float red[H_HEADS][NPREV][8];
    __shared__ __align__(16) float attn_s[H_HEADS][NPREV];

    const int m    = blockIdx.x;
    const int tid  = threadIdx.x;
    const int lane = tid & 31;
    const int warp = tid >> 5;

    const __nv_bfloat16* qrow = qk + (size_t)m * (H_HEADS * D_DIM) + tid * 4;
    uint2 q2[H_HEADS];
#pragma unroll
    for (int h = 0; h < H_HEADS; h++)
        q2[h] = *(const uint2*)(qrow + h * D_DIM);

    float4 hv[NPREV];
    const float* hg = hist + (size_t)m * NPREV * D_DIM + tid * 4;
#pragma unroll
    for (int n = 0; n < NPREV; n++)
        hv[n] = *(const float4*)(hg + n * D_DIM);

    // ---- Phase A: dots + multi-value butterfly reduction ----
#pragma unroll
    for (int h = 0; h < H_HEADS; h++) {
        float2 qa = __bfloat1622float2(*reinterpret_cast<__nv_bfloat162*>(&q2[h].x));
        float2 qb = __bfloat1622float2(*reinterpret_cast<__nv_bfloat162*>(&q2[h].y));
        float p[NPREV];
#pragma unroll
        for (int n = 0; n < NPREV; n++)
            p[n] = qa.x * hv[n].x + qa.y * hv[n].y
                 + qb.x * hv[n].z + qb.y * hv[n].w;

#pragma unroll
        for (int i = 0; i < 4; i++) {
            float send = (lane & 16) ? p[i] : p[i + 4];
            float recv = __shfl_xor_sync(0xffffffffu, send, 16);
            p[i] = ((lane & 16) ? p[i + 4] : p[i]) + recv;
        }
#pragma unroll
        for (int i = 0; i < 2; i++) {
            float send = (lane & 8) ? p[i] : p[i + 2];
            float recv = __shfl_xor_sync(0xffffffffu, send, 8);
            p[i] = ((lane & 8) ? p[i + 2] : p[i]) + recv;
        }
        {
            float send = (lane & 4) ? p[0] : p[1];
            float recv = __shfl_xor_sync(0xffffffffu, send, 4);
            p[0] = ((lane & 4) ? p[1] : p[0]) + recv;
        }
        p[0] += __shfl_xor_sync(0xffffffffu, p[0], 2);
        p[0] += __shfl_xor_sync(0xffffffffu, p[0], 1);
        if ((lane & 3) == 0) red[h][lane >> 2][warp] = p[0];
    }
    __syncthreads();

    // ---- Phase B: 16 parallel softmaxes ----
    if (tid < H_HEADS) {
        const int h = tid;
        float lg[NPREV];
        float mx = -1e30f;
#pragma unroll
        for (int n = 0; n < NPREV; n++) {
            float4 s0 = *(const float4*)&red[h][n][0];
            float4 s1 = *(const float4*)&red[h][n][4];
            float s = (s0.x + s0.y) + (s0.z + s0.w)
                    + (s1.x + s1.y) + (s1.z + s1.w);
            lg[n] = s * 0.125f;
            mx = fmaxf(mx, lg[n]);
        }
        float den = 0.0f;
#pragma unroll
        for (int n = 0; n < NPREV; n++) { lg[n] = expf(lg[n] - mx); den += lg[n]; }
        float inv = 1.0f / den;
#pragma unroll
        for (int n = 0; n < NPREV; n++) attn_s[h][n] = lg[n] * inv;
    }
    __syncthreads();

    // ---- Phase C: weighted sums + bf16 stores ----
    __nv_bfloat16* orow = hbar + (size_t)m * (H_HEADS * D_DIM) + tid * 4;
#pragma unroll
    for (int h = 0; h < H_HEADS; h++) {
        float4 w0 = *(const float4*)&attn_s[h][0];
        float4 w1 = *(const float4*)&attn_s[h][4];
        float4 a4;
        a4.x = w0.x * hv[0].x; a4.y = w0.x * hv[0].y;
        a4.z = w0.x * hv[0].z; a4.w = w0.x * hv[0].w;
        a4.x = fmaf(w0.y, hv[1].x, a4.x); a4.y = fmaf(w0.y, hv[1].y, a4.y);
        a4.z = fmaf(w0.y, hv[1].z, a4.z); a4.w = fmaf(w0.y, hv[1].w, a4.w);
        a4.x = fmaf(w0.z, hv[2].x, a4.x); a4.y = fmaf(w0.z, hv[2].y, a4.y);
        a4.z = fmaf(w0.z, hv[2].z, a4.z); a4.w = fmaf(w0.z, hv[2].w, a4.w);
        a4.x = fmaf(w0.w, hv[3].x, a4.x); a4.y = fmaf(w0.w, hv[3].y, a4.y);
        a4.z = fmaf(w0.w, hv[3].z, a4.z); a4.w = fmaf(w0.w, hv[3].w, a4.w);
        a4.x = fmaf(w1.x, hv[4].x, a4.x); a4.y = fmaf(w1.x, hv[4].y, a4.y);
        a4.z = fmaf(w1.x, hv[4].z, a4.z); a4.w = fmaf(w1.x, hv[4].w, a4.w);
        a4.x = fmaf(w1.y, hv[5].x, a4.x); a4.y = fmaf(w1.y, hv[5].y, a4.y);
        a4.z = fmaf(w1.y, hv[5].z, a4.z); a4.w = fmaf(w1.y, hv[5].w, a4.w);
        a4.x = fmaf(w1.z, hv[6].x, a4.x); a4.y = fmaf(w1.z, hv[6].y, a4.y);
        a4.z = fmaf(w1.z, hv[6].z, a4.z); a4.w = fmaf(w1.z, hv[6].w, a4.w);
        a4.x = fmaf(w1.w, hv[7].x, a4.x); a4.y = fmaf(w1.w, hv[7].y, a4.y);
        a4.z = fmaf(w1.w, hv[7].z, a4.z); a4.w = fmaf(w1.w, hv[7].w, a4.w);
        uint2 ov;
        ov.x = pack_bf162(a4.x, a4.y);
        ov.y = pack_bf162(a4.z, a4.w);
        *(uint2*)(orow + h * D_DIM) = ov;
    }
}

// ---------------------------------------------------------------------------
extern "C" void kernel_launch(void* const* d_in, const int* in_sizes, int n_in,
                              void* d_out, int out_size)
{
    const float* cur  = (const float*)d_in[0];
    const float* hist = (const float*)d_in[1];
    const float* Wq   = (const float*)d_in[2];
    const float* Wk   = (const float*)d_in[3];
    const float* Wv   = (const float*)d_in[4];
    const float* Wo   = (const float*)d_in[5];
    float* out = (float*)d_out;

    const int D = D_DIM;
    const int M = in_sizes[0] / D;   // 8192

    __nv_bfloat16 *cb = nullptr, *qb = nullptr, *qk = nullptr, *hb = nullptr;
    __nv_bfloat16 *ob = nullptr, *wq = nullptr, *wkt = nullptr, *wv = nullptr, *wo = nullptr;
    cudaGetSymbolAddress((void**)&cb,  g_cb);
    cudaGetSymbolAddress((void**)&qb,  g_qb);
    cudaGetSymbolAddress((void**)&qk,  g_qk);
    cudaGetSymbolAddress((void**)&hb,  g_hb);
    cudaGetSymbolAddress((void**)&ob,  g_ob);
    cudaGetSymbolAddress((void**)&wq,  g_wq);
    cudaGetSymbolAddress((void**)&wkt, g_wkt);
    cudaGetSymbolAddress((void**)&wv,  g_wv);
    cudaGetSymbolAddress((void**)&wo,  g_wo);

    // SMEM budgets (bytes)
    constexpr int SM_K2   = (128 * 72 + 2 * (128 * 72) + 128 * 136) * 2;  // 90112
    constexpr int SM_B64  = (2 * (128 * 72) + 2 * (64 * 72)) * 2;         // 55296
    constexpr int SM_B128 = (2 * (128 * 72) + 2 * (128 * 72)) * 2;        // 73728

    cudaFuncSetAttribute(gemm_k2,
                         cudaFuncAttributeMaxDynamicSharedMemorySize, SM_K2);
    cudaFuncSetAttribute(gemm_bf16<64, true,  false>,
                         cudaFuncAttributeMaxDynamicSharedMemorySize, SM_B64);
    cudaFuncSetAttribute(gemm_bf16<128, true,  false>,
                         cudaFuncAttributeMaxDynamicSharedMemorySize, SM_B128);
    cudaFuncSetAttribute(gemm_bf16<128, false, true>,
                         cudaFuncAttributeMaxDynamicSharedMemorySize, SM_B128);

    // P0: one fused conversion launch + Wk transpose
    const int nb_cur = M * D / 4 / 256;        // 8192 blocks
    const int nb_w   = D * D / 4 / 256;        // 1024 blocks each
    convert_all<<<nb_cur + 3 * nb_w, 256>>>(
        cur, cb, Wq, wq, Wv, wv, Wo, wo, nb_cur, nb_w);
    transpose_wk_bf16<<<dim3(32, 32), dim3(32, 8)>>>(Wk, wkt);

    // K1: q = cur @ Wq^T  (bf16, BN=128, 2-stage) -> bf16
    gemm_bf16<128, true, false>
        <<<dim3(D / 128, M / 128, 1), 256, SM_B128>>>(
            cb, D, 0, wq, D, 0, nullptr, qb, D, 0, D);

    // K2: qk_h = q_h @ Wk_h  (bf16, persistent j-loop, staged) -> bf16
    gemm_k2<<<dim3(M / 128, H_HEADS), 256, SM_K2>>>(qb, wkt, qk);

    // K3: attention -> hbar (bf16)
    attn_kernel<<<M, 256>>>(hist, qk, hb);

    // K4: out_h = hbar_h @ Wv_h^T (bf16, BN=64) -> out bf16
    gemm_bf16<64, true, false>
        <<<dim3(1, M / 128, H_HEADS), 256, SM_B64>>>(
            hb, H_HEADS * D, D,
            wv, D, (long long)HD * D,
            nullptr,
            ob, D, HD,
            D);

    // K5: final = cur + out @ Wo^T  (bf16, BN=128 + fp32 residual)
    gemm_bf16<128, false, true>
        <<<dim3(D / 128, M / 128, 1), 256, SM_B128>>>(
            ob, D, 0, wo, D, 0, cur, out, D, 0, D);
}